// round 4
// baseline (speedup 1.0000x reference)
#include <cuda_runtime.h>
#include <cfloat>

#define EPS_S   0.01f
#define INV_EPS 100.0f
#define LOG_MU  -6.93146200f   /* log(1/1024 + 1e-8) */
#define BN_EPS  1e-5f

/* ---------------- scratch (device globals: no allocs allowed) -------------- */
__device__ float g_C[4 * 1024 * 1024];
__device__ float g_u[4096], g_v[4096];
__device__ float g_rnx[4096], g_rny[4096];
__device__ float g_t[4 * 512 * 1024];
__device__ float g_a1[4 * 256 * 1024];
__device__ float g_a2[4 * 256 * 1024];
__device__ float g_alpha[4 * 512 * 1024];
__device__ float g_cm[2048], g_rs[2048];
__device__ float g_scale[512], g_shift[512];

/* ---------------- fast exp on the FMA pipe (no MUFU) ----------------
   exp(x) = e^f * 2^n, n = rint(x*log2e), f = (x*log2e - n)*ln2.
   Degree-6 Taylor on |f| <= 0.3466: rel err ~2e-7. Args <= ~+10 here. */
__device__ __forceinline__ float fexp(float x) {
    float y = x * 1.44269504f;
    y = fmaxf(y, -126.f);
    int ni = __float2int_rn(y);
    float n = (float)ni;
    float f = (y - n) * 0.69314718056f;
    float p = 1.3888889e-3f;
    p = fmaf(p, f, 8.3333333e-3f);
    p = fmaf(p, f, 4.1666667e-2f);
    p = fmaf(p, f, 1.6666667e-1f);
    p = fmaf(p, f, 0.5f);
    p = fmaf(p, f, 1.0f);
    p = fmaf(p, f, 1.0f);
    float s = __int_as_float((ni + 127) << 23);
    return p * s;
}

/* ---------------- small helpers ---------------- */
__device__ __forceinline__ float warpMax(float v) {
    #pragma unroll
    for (int o = 16; o; o >>= 1) v = fmaxf(v, __shfl_xor_sync(0xffffffffu, v, o));
    return v;
}
__device__ __forceinline__ float warpSum(float v) {
    #pragma unroll
    for (int o = 16; o; o >>= 1) v += __shfl_xor_sync(0xffffffffu, v, o);
    return v;
}

/* ---------------- 1/||x|| per point ---------------- */
__global__ __launch_bounds__(256) void rownorm(const float* __restrict__ x,
                                               float* __restrict__ rn) {
    int b = blockIdx.y;
    int i = blockIdx.x * 256 + threadIdx.x;
    const float* p = x + ((size_t)b * 512 << 10) + i;
    float s = 0.f;
    #pragma unroll 8
    for (int d = 0; d < 512; d++) {
        float v = p[(size_t)d << 10];
        s = fmaf(v, v, s);
    }
    rn[(b << 10) + i] = rsqrtf(s);
}

/* ---------------- SGEMM TN (double-buffered): cost matrix ------------------ */
#define BM 128
#define BN 128
#define BK 16
__global__ __launch_bounds__(256) void gemm_tn_cost(
    const float* __restrict__ A, const float* __restrict__ B,
    const float* __restrict__ rnx, const float* __restrict__ rny,
    float* __restrict__ Cout) {
    int b = blockIdx.z;
    const float* Ab = A + (size_t)b * 512 * 1024;
    const float* Bb = B + (size_t)b * 512 * 1024;
    float* Cb = Cout + (size_t)b * 1024 * 1024;
    __shared__ float As[2][BK][BM];
    __shared__ float Bs[2][BK][BN];
    int tid = threadIdx.x;
    int tx = tid & 15, ty = tid >> 4;
    int m0 = blockIdx.x * BM, n0 = blockIdx.y * BN;
    int lk[2], lm4[2];
    #pragma unroll
    for (int l = 0; l < 2; l++) { int idx = tid + l * 256; lk[l] = idx >> 5; lm4[l] = idx & 31; }
    float acc[8][8];
    #pragma unroll
    for (int i = 0; i < 8; i++)
        #pragma unroll
        for (int j = 0; j < 8; j++) acc[i][j] = 0.f;

    #pragma unroll
    for (int l = 0; l < 2; l++) {
        *(float4*)&As[0][lk[l]][lm4[l] * 4] =
            *(const float4*)(Ab + (size_t)lk[l] * 1024 + m0 + lm4[l] * 4);
        *(float4*)&Bs[0][lk[l]][lm4[l] * 4] =
            *(const float4*)(Bb + (size_t)lk[l] * 1024 + n0 + lm4[l] * 4);
    }
    __syncthreads();
    int cur = 0;
    for (int k0 = 0; k0 < 512; k0 += BK) {
        int nk0 = k0 + BK;
        float4 pa[2], pb[2];
        if (nk0 < 512) {
            #pragma unroll
            for (int l = 0; l < 2; l++) {
                pa[l] = *(const float4*)(Ab + (size_t)(nk0 + lk[l]) * 1024 + m0 + lm4[l] * 4);
                pb[l] = *(const float4*)(Bb + (size_t)(nk0 + lk[l]) * 1024 + n0 + lm4[l] * 4);
            }
        }
        #pragma unroll
        for (int k = 0; k < BK; k++) {
            float a[8], bb[8];
            *(float4*)a       = *(float4*)&As[cur][k][ty * 8];
            *(float4*)(a + 4) = *(float4*)&As[cur][k][ty * 8 + 4];
            *(float4*)bb       = *(float4*)&Bs[cur][k][tx * 8];
            *(float4*)(bb + 4) = *(float4*)&Bs[cur][k][tx * 8 + 4];
            #pragma unroll
            for (int i = 0; i < 8; i++)
                #pragma unroll
                for (int j = 0; j < 8; j++) acc[i][j] = fmaf(a[i], bb[j], acc[i][j]);
        }
        if (nk0 < 512) {
            #pragma unroll
            for (int l = 0; l < 2; l++) {
                *(float4*)&As[cur ^ 1][lk[l]][lm4[l] * 4] = pa[l];
                *(float4*)&Bs[cur ^ 1][lk[l]][lm4[l] * 4] = pb[l];
            }
        }
        __syncthreads();
        cur ^= 1;
    }
    #pragma unroll
    for (int i = 0; i < 8; i++) {
        int m = m0 + ty * 8 + i;
        float rx = rnx[(b << 10) + m];
        float4 o0, o1;
        #pragma unroll
        for (int j = 0; j < 8; j++) {
            int n = n0 + tx * 8 + j;
            float v = 1.f - rx * rny[(b << 10) + n] * acc[i][j];
            if (j < 4) ((float*)&o0)[j] = v; else ((float*)&o1)[j - 4] = v;
        }
        *(float4*)(Cb + (size_t)m * 1024 + n0 + tx * 8)     = o0;
        *(float4*)(Cb + (size_t)m * 1024 + n0 + tx * 8 + 4) = o1;
    }
}

/* ---- SGEMM NT (double-buffered) with fused pi = exp((u+v-C)/eps)*1024 ----- */
__global__ __launch_bounds__(256) void gemm_nt_t(
    const float* __restrict__ A,
    const float* __restrict__ Cc,
    const float* __restrict__ u, const float* __restrict__ v,
    float* __restrict__ T) {
    int b = blockIdx.z;
    const float* Ab = A + (size_t)b * 512 * 1024;
    const float* Pb = Cc + (size_t)b * 1024 * 1024;
    const float* ub = u + (b << 10);
    const float* vb = v + (b << 10);
    float* Tb = T + (size_t)b * 512 * 1024;
    __shared__ float As[2][BK][BM];
    __shared__ float Bs[2][BK][BN];
    int tid = threadIdx.x;
    int tx = tid & 15, ty = tid >> 4;
    int m0 = blockIdx.x * BM, n0 = blockIdx.y * BN;
    int lm[2], lk4[2];
    #pragma unroll
    for (int l = 0; l < 2; l++) { int idx = tid + l * 256; lm[l] = idx >> 2; lk4[l] = idx & 3; }
    float myui[2];
    #pragma unroll
    for (int l = 0; l < 2; l++) myui[l] = ub[n0 + lm[l]];
    float acc[8][8];
    #pragma unroll
    for (int i = 0; i < 8; i++)
        #pragma unroll
        for (int j = 0; j < 8; j++) acc[i][j] = 0.f;

    /* preload tile 0 */
    #pragma unroll
    for (int l = 0; l < 2; l++) {
        float4 va = *(const float4*)(Ab + (size_t)(m0 + lm[l]) * 1024 + lk4[l] * 4);
        As[0][lk4[l] * 4 + 0][lm[l]] = va.x; As[0][lk4[l] * 4 + 1][lm[l]] = va.y;
        As[0][lk4[l] * 4 + 2][lm[l]] = va.z; As[0][lk4[l] * 4 + 3][lm[l]] = va.w;
        float4 vc = *(const float4*)(Pb + (size_t)(n0 + lm[l]) * 1024 + lk4[l] * 4);
        float4 vv = *(const float4*)(vb + lk4[l] * 4);
        Bs[0][lk4[l] * 4 + 0][lm[l]] = fexp((myui[l] + vv.x - vc.x) * INV_EPS) * 1024.f;
        Bs[0][lk4[l] * 4 + 1][lm[l]] = fexp((myui[l] + vv.y - vc.y) * INV_EPS) * 1024.f;
        Bs[0][lk4[l] * 4 + 2][lm[l]] = fexp((myui[l] + vv.z - vc.z) * INV_EPS) * 1024.f;
        Bs[0][lk4[l] * 4 + 3][lm[l]] = fexp((myui[l] + vv.w - vc.w) * INV_EPS) * 1024.f;
    }
    __syncthreads();
    int cur = 0;
    for (int k0 = 0; k0 < 1024; k0 += BK) {
        int nk0 = k0 + BK;
        float4 pa[2], pc[2], pvv[2];
        if (nk0 < 1024) {
            #pragma unroll
            for (int l = 0; l < 2; l++) {
                pa[l] = *(const float4*)(Ab + (size_t)(m0 + lm[l]) * 1024 + nk0 + lk4[l] * 4);
                pc[l] = *(const float4*)(Pb + (size_t)(n0 + lm[l]) * 1024 + nk0 + lk4[l] * 4);
                pvv[l] = *(const float4*)(vb + nk0 + lk4[l] * 4);
            }
        }
        #pragma unroll
        for (int k = 0; k < BK; k++) {
            float a[8], bb[8];
            *(float4*)a       = *(float4*)&As[cur][k][ty * 8];
            *(float4*)(a + 4) = *(float4*)&As[cur][k][ty * 8 + 4];
            *(float4*)bb       = *(float4*)&Bs[cur][k][tx * 8];
            *(float4*)(bb + 4) = *(float4*)&Bs[cur][k][tx * 8 + 4];
            #pragma unroll
            for (int i = 0; i < 8; i++)
                #pragma unroll
                for (int j = 0; j < 8; j++) acc[i][j] = fmaf(a[i], bb[j], acc[i][j]);
        }
        if (nk0 < 1024) {
            #pragma unroll
            for (int l = 0; l < 2; l++) {
                int nb = cur ^ 1;
                As[nb][lk4[l] * 4 + 0][lm[l]] = pa[l].x;
                As[nb][lk4[l] * 4 + 1][lm[l]] = pa[l].y;
                As[nb][lk4[l] * 4 + 2][lm[l]] = pa[l].z;
                As[nb][lk4[l] * 4 + 3][lm[l]] = pa[l].w;
                Bs[nb][lk4[l] * 4 + 0][lm[l]] = fexp((myui[l] + pvv[l].x - pc[l].x) * INV_EPS) * 1024.f;
                Bs[nb][lk4[l] * 4 + 1][lm[l]] = fexp((myui[l] + pvv[l].y - pc[l].y) * INV_EPS) * 1024.f;
                Bs[nb][lk4[l] * 4 + 2][lm[l]] = fexp((myui[l] + pvv[l].z - pc[l].z) * INV_EPS) * 1024.f;
                Bs[nb][lk4[l] * 4 + 3][lm[l]] = fexp((myui[l] + pvv[l].w - pc[l].w) * INV_EPS) * 1024.f;
            }
        }
        __syncthreads();
        cur ^= 1;
    }
    #pragma unroll
    for (int i = 0; i < 8; i++) {
        int m = m0 + ty * 8 + i;
        float4 o0, o1;
        #pragma unroll
        for (int j = 0; j < 8; j++) {
            float vvv = acc[i][j];
            if (j < 4) ((float*)&o0)[j] = vvv; else ((float*)&o1)[j - 4] = vvv;
        }
        *(float4*)(Tb + (size_t)m * 1024 + n0 + tx * 8)     = o0;
        *(float4*)(Tb + (size_t)m * 1024 + n0 + tx * 8 + 4) = o1;
    }
}

/* ---------------- Sinkhorn ---------------- */
__global__ void zero_uv(float* u, float* v) {
    int i = blockIdx.x * blockDim.x + threadIdx.x;
    if (i < 4096) { u[i] = 0.f; v[i] = 0.f; }
}

__global__ __launch_bounds__(256) void u_update(const float* __restrict__ C,
                                                const float* __restrict__ v,
                                                float* __restrict__ u) {
    int b = blockIdx.y, i = blockIdx.x, t = threadIdx.x;
    const float4* C4 = (const float4*)(C + ((size_t)(b << 10) + i) * 1024);
    const float4* V4 = (const float4*)(v + (b << 10));
    float4 c = C4[t], vv = V4[t];
    float x0 = (vv.x - c.x) * INV_EPS;
    float x1 = (vv.y - c.y) * INV_EPS;
    float x2 = (vv.z - c.z) * INV_EPS;
    float x3 = (vv.w - c.w) * INV_EPS;
    float mx = fmaxf(fmaxf(x0, x1), fmaxf(x2, x3));
    __shared__ float redm[8], redq[8];
    mx = warpMax(mx);
    if ((t & 31) == 0) redm[t >> 5] = mx;
    __syncthreads();
    if (t < 32) {
        float z = (t < 8) ? redm[t] : -FLT_MAX;
        #pragma unroll
        for (int o = 4; o; o >>= 1) z = fmaxf(z, __shfl_xor_sync(0xffffffffu, z, o));
        if (t == 0) redm[0] = z;
    }
    __syncthreads();
    float bm = redm[0];
    float s = fexp(x0 - bm) + fexp(x1 - bm) + fexp(x2 - bm) + fexp(x3 - bm);
    s = warpSum(s);
    if ((t & 31) == 0) redq[t >> 5] = s;
    __syncthreads();
    if (t == 0) {
        float z = 0.f;
        #pragma unroll
        for (int q = 0; q < 8; q++) z += redq[q];
        u[(b << 10) + i] = EPS_S * (LOG_MU - (bm + __logf(z)));
    }
}

__global__ __launch_bounds__(256) void v_update(const float* __restrict__ C,
                                                const float* __restrict__ u,
                                                float* __restrict__ v) {
    int b = blockIdx.y;
    int tx = threadIdx.x, ty = threadIdx.y;
    int j = blockIdx.x * 32 + tx;
    const float* p = C + (size_t)b * 1048576 + j;
    const float* ub = u + (b << 10);
    float m0 = -FLT_MAX, s0 = 0.f, m1 = -FLT_MAX, s1 = 0.f;
    for (int i = ty; i < 1024; i += 16) {
        float xa = (ub[i] - p[(size_t)i << 10]) * INV_EPS;
        float xb = (ub[i + 8] - p[(size_t)(i + 8) << 10]) * INV_EPS;
        float n0 = fmaxf(m0, xa);
        s0 = s0 * fexp(m0 - n0) + fexp(xa - n0); m0 = n0;
        float n1 = fmaxf(m1, xb);
        s1 = s1 * fexp(m1 - n1) + fexp(xb - n1); m1 = n1;
    }
    float mm = fmaxf(m0, m1);
    float ss = s0 * fexp(m0 - mm) + s1 * fexp(m1 - mm);
    __shared__ float sm[8][32], sq[8][32];
    sm[ty][tx] = mm; sq[ty][tx] = ss;
    __syncthreads();
    if (ty == 0) {
        float M = mm, S = ss;
        #pragma unroll
        for (int q = 1; q < 8; q++) {
            float m2 = sm[q][tx], s2 = sq[q][tx];
            float nm = fmaxf(M, m2);
            S = S * fexp(M - nm) + s2 * fexp(m2 - nm);
            M = nm;
        }
        v[(b << 10) + j] = EPS_S * (LOG_MU - (M + __logf(S)));
    }
}

/* ---------------- per-(b,c) mean / 1/std of content ---------------- */
__global__ __launch_bounds__(128) void cmstd(const float* __restrict__ x,
                                             float* __restrict__ cm,
                                             float* __restrict__ rs) {
    int bc = blockIdx.x, t = threadIdx.x;
    const float* p = x + ((size_t)bc << 10);
    float s = 0.f, q = 0.f;
    #pragma unroll
    for (int l = 0; l < 8; l++) {
        float v = p[t + l * 128];
        s += v; q = fmaf(v, v, q);
    }
    s = warpSum(s); q = warpSum(q);
    __shared__ float rsm[4], rqm[4];
    if ((t & 31) == 0) { rsm[t >> 5] = s; rqm[t >> 5] = q; }
    __syncthreads();
    if (t == 0) {
        float S = rsm[0] + rsm[1] + rsm[2] + rsm[3];
        float Q = rqm[0] + rqm[1] + rqm[2] + rqm[3];
        float mean = S * (1.f / 1024.f);
        float var = Q * (1.f / 1024.f) - mean * mean;
        cm[bc] = mean;
        rs[bc] = rsqrtf(fmaxf(var, 0.f) + 1e-5f);
    }
}

/* ---------------- BatchNorm stats (train mode): scale/shift ---------------- */
__global__ __launch_bounds__(256) void bnstats(const float* __restrict__ x,
                                               const float* __restrict__ g,
                                               const float* __restrict__ be,
                                               int CO, float* __restrict__ scale,
                                               float* __restrict__ shift) {
    int c = blockIdx.x, t = threadIdx.x;
    float s = 0.f, q = 0.f;
    #pragma unroll
    for (int l = 0; l < 16; l++) {
        int idx = t + (l << 8);
        int bb = idx >> 10, p = idx & 1023;
        float v = x[((size_t)(bb * CO + c) << 10) + p];
        s += v; q = fmaf(v, v, q);
    }
    s = warpSum(s); q = warpSum(q);
    __shared__ float rsm[8], rqm[8];
    if ((t & 31) == 0) { rsm[t >> 5] = s; rqm[t >> 5] = q; }
    __syncthreads();
    if (t == 0) {
        float S = 0.f, Q = 0.f;
        #pragma unroll
        for (int w = 0; w < 8; w++) { S += rsm[w]; Q += rqm[w]; }
        float mean = S * (1.f / 4096.f);
        float var = Q * (1.f / 4096.f) - mean * mean;
        float sc = g[c] * rsqrtf(fmaxf(var, 0.f) + BN_EPS);
        scale[c] = sc;
        shift[c] = be[c] - mean * sc;
    }
}

/* ---------------- direct 3x3 conv, double-buffered smem tiles ---------------
   optional fused per-input-channel affine (BN apply) and fused blend
   (decoder: v = t + alpha*(content-cm)*rs).                                  */
template <int OCT, int SROWS, int NT, int CIT>
__global__ __launch_bounds__(NT) void conv3x3(
    const float* __restrict__ src0, const float* __restrict__ src1, int csplit,
    const float* __restrict__ sc, const float* __restrict__ sh,
    const float* __restrict__ bl_a, const float* __restrict__ bl_x,
    const float* __restrict__ bl_cm, const float* __restrict__ bl_rs,
    int CI, int CO, const float* __restrict__ W, const float* __restrict__ bias,
    float* __restrict__ out, int relu) {
    constexpr int NPIX = SROWS * 32;
    constexpr int PXT = NPIX / NT;
    constexpr int ROWSP = SROWS + 2;
    constexpr int TOTIN = CIT * ROWSP * 34;
    constexpr int TW = CIT * 9 * OCT;
    constexpr int NIN = (TOTIN + NT - 1) / NT;
    constexpr int NWW = (TW + NT - 1) / NT;
    __shared__ float s_in[2][CIT][ROWSP][34];
    __shared__ float s_w[2][CIT][9][OCT];
    int b = blockIdx.x, oc0 = blockIdx.y * OCT, r0 = blockIdx.z * SROWS;
    int tid = threadIdx.x;
    int rr[PXT], cc[PXT];
    #pragma unroll
    for (int p = 0; p < PXT; p++) {
        int px = tid + p * NT;
        rr[p] = px >> 5; cc[p] = px & 31;
    }
    float acc[OCT][PXT];
    #pragma unroll
    for (int o = 0; o < OCT; o++)
        #pragma unroll
        for (int p = 0; p < PXT; p++) acc[o][p] = 0.f;

    int use_aff = (sc != nullptr);
    int use_blend = (bl_a != nullptr);
    float rin[NIN], rw[NWW];

    /* prefetch helper (inlined twice via macro) */
#define PREFETCH(CI0)                                                          \
    {                                                                          \
        int ci0_ = (CI0);                                                      \
        _Pragma("unroll")                                                      \
        for (int l = 0; l < NIN; l++) {                                        \
            int idx = tid + l * NT;                                            \
            float v = 0.f;                                                     \
            if (idx < TOTIN) {                                                 \
                int ci = idx / (ROWSP * 34);                                   \
                int rem = idx - ci * (ROWSP * 34);                             \
                int r = rem / 34, c = rem - r * 34;                            \
                int gy = r0 + r - 1, gx = c - 1;                               \
                if ((unsigned)gy < 32u && (unsigned)gx < 32u) {                \
                    int cig = ci0_ + ci;                                       \
                    int pix = (gy << 5) + gx;                                  \
                    const float* s = (cig < csplit)                            \
                        ? (src0 + ((size_t)(b * csplit + cig) << 10))          \
                        : (src1 + ((size_t)(b * (CI - csplit) + (cig - csplit)) << 10)); \
                    v = s[pix];                                                \
                    if (use_aff) v = fmaf(v, sc[cig], sh[cig]);                \
                    if (use_blend) {                                           \
                        int ch = b * CI + cig;                                 \
                        size_t off = ((size_t)ch << 10) + pix;                 \
                        v = fmaf(bl_a[off], (bl_x[off] - bl_cm[ch]) * bl_rs[ch], v); \
                    }                                                          \
                }                                                              \
            }                                                                  \
            rin[l] = v;                                                        \
        }                                                                      \
        _Pragma("unroll")                                                      \
        for (int l = 0; l < NWW; l++) {                                        \
            int idx = tid + l * NT;                                            \
            float wv = 0.f;                                                    \
            if (idx < TW) {                                                    \
                int ci = idx / (9 * OCT);                                      \
                int rem = idx - ci * (9 * OCT);                                \
                int k = rem / OCT, oc = rem - k * OCT;                         \
                if (oc0 + oc < CO)                                             \
                    wv = W[((size_t)(oc0 + oc) * CI + ci0_ + ci) * 9 + k];     \
            }                                                                  \
            rw[l] = wv;                                                        \
        }                                                                      \
    }

#define STORE(BUF)                                                             \
    {                                                                          \
        _Pragma("unroll")                                                      \
        for (int l = 0; l < NIN; l++) {                                        \
            int idx = tid + l * NT;                                            \
            if (idx < TOTIN) (&s_in[BUF][0][0][0])[idx] = rin[l];              \
        }                                                                      \
        _Pragma("unroll")                                                      \
        for (int l = 0; l < NWW; l++) {                                        \
            int idx = tid + l * NT;                                            \
            if (idx < TW) (&s_w[BUF][0][0][0])[idx] = rw[l];                   \
        }                                                                      \
    }

    PREFETCH(0)
    STORE(0)
    __syncthreads();
    int cur = 0;
    #pragma unroll 1
    for (int ci0 = 0; ci0 < CI; ci0 += CIT) {
        int nci0 = ci0 + CIT;
        if (nci0 < CI) PREFETCH(nci0)
        #pragma unroll 1
        for (int ci = 0; ci < CIT; ci++) {
            #pragma unroll
            for (int ky = 0; ky < 3; ky++)
                #pragma unroll
                for (int kx = 0; kx < 3; kx++) {
                    float w[OCT];
                    #pragma unroll
                    for (int o4 = 0; o4 < OCT / 4; o4++)
                        *(float4*)&w[o4 * 4] = *(const float4*)&s_w[cur][ci][ky * 3 + kx][o4 * 4];
                    #pragma unroll
                    for (int p = 0; p < PXT; p++) {
                        float v = s_in[cur][ci][rr[p] + ky][cc[p] + kx];
                        #pragma unroll
                        for (int o = 0; o < OCT; o++)
                            acc[o][p] = fmaf(v, w[o], acc[o][p]);
                    }
                }
        }
        if (nci0 < CI) STORE(cur ^ 1)
        __syncthreads();
        cur ^= 1;
    }
#undef PREFETCH
#undef STORE
    #pragma unroll
    for (int o = 0; o < OCT; o++) {
        if (oc0 + o >= CO) break;
        float bi = bias[oc0 + o];
        #pragma unroll
        for (int p = 0; p < PXT; p++) {
            float v = acc[o][p] + bi;
            if (relu) v = fmaxf(v, 0.f);
            out[((size_t)(b * CO + oc0 + o) << 10) + r0 * 32 + tid + p * NT] = v;
        }
    }
}

/* ---------------- host orchestration ---------------- */
extern "C" void kernel_launch(void* const* d_in, const int* in_sizes, int n_in,
                              void* d_out, int out_size) {
    const float* content = (const float*)d_in[0];
    const float* style   = (const float*)d_in[1];
    const float* w1 = (const float*)d_in[2];  const float* b1 = (const float*)d_in[3];
    const float* g1 = (const float*)d_in[4];  const float* be1 = (const float*)d_in[5];
    const float* w2 = (const float*)d_in[6];  const float* b2 = (const float*)d_in[7];
    const float* g2 = (const float*)d_in[8];  const float* be2 = (const float*)d_in[9];
    const float* w3 = (const float*)d_in[10]; const float* b3 = (const float*)d_in[11];
    const float* dw = (const float*)d_in[12]; const float* db = (const float*)d_in[13];
    float* out = (float*)d_out;
    (void)in_sizes; (void)n_in; (void)out_size;

    float *pC, *pu, *pv, *prnx, *prny, *pt, *pa1, *pa2, *palpha, *pcm, *prs, *pscale, *pshift;
    cudaGetSymbolAddress((void**)&pC, g_C);
    cudaGetSymbolAddress((void**)&pu, g_u);
    cudaGetSymbolAddress((void**)&pv, g_v);
    cudaGetSymbolAddress((void**)&prnx, g_rnx);
    cudaGetSymbolAddress((void**)&prny, g_rny);
    cudaGetSymbolAddress((void**)&pt, g_t);
    cudaGetSymbolAddress((void**)&pa1, g_a1);
    cudaGetSymbolAddress((void**)&pa2, g_a2);
    cudaGetSymbolAddress((void**)&palpha, g_alpha);
    cudaGetSymbolAddress((void**)&pcm, g_cm);
    cudaGetSymbolAddress((void**)&prs, g_rs);
    cudaGetSymbolAddress((void**)&pscale, g_scale);
    cudaGetSymbolAddress((void**)&pshift, g_shift);

    /* cosine-cost matrix */
    rownorm<<<dim3(4, 4), 256>>>(content, prnx);
    rownorm<<<dim3(4, 4), 256>>>(style, prny);
    gemm_tn_cost<<<dim3(8, 8, 4), 256>>>(content, style, prnx, prny, pC);

    /* Sinkhorn, 20 iterations */
    zero_uv<<<16, 256>>>(pu, pv);
    for (int it = 0; it < 20; it++) {
        u_update<<<dim3(1024, 4), 256>>>(pC, pv, pu);
        v_update<<<dim3(32, 4), dim3(32, 8)>>>(pC, pu, pv);
    }

    /* t = pi @ style_points, exp fused into B-tile load */
    gemm_nt_t<<<dim3(4, 8, 4), 256>>>(style, pC, pu, pv, pt);

    /* content per-channel mean/std */
    cmstd<<<2048, 128>>>(content, pcm, prs);

    /* alpha predictor (BN-apply fused into next conv's input load) */
    conv3x3<8, 16, 256, 8><<<dim3(4, 32, 2), 256>>>(pt, content, 512,
        nullptr, nullptr, nullptr, nullptr, nullptr, nullptr,
        1024, 256, w1, b1, pa1, 1);
    bnstats<<<256, 256>>>(pa1, g1, be1, 256, pscale, pshift);
    conv3x3<8, 16, 256, 8><<<dim3(4, 32, 2), 256>>>(pa1, pa1, 256,
        pscale, pshift, nullptr, nullptr, nullptr, nullptr,
        256, 256, w2, b2, pa2, 1);
    bnstats<<<256, 256>>>(pa2, g2, be2, 256, pscale, pshift);
    conv3x3<8, 16, 256, 8><<<dim3(4, 64, 2), 256>>>(pa2, pa2, 256,
        pscale, pshift, nullptr, nullptr, nullptr, nullptr,
        256, 512, w3, b3, palpha, 0);

    /* decoder conv with fused blend: in = t + alpha*(content-cm)*rs */
    conv3x3<4, 4, 128, 8><<<dim3(4, 1, 8), 128>>>(pt, pt, 512,
        nullptr, nullptr, palpha, content, pcm, prs,
        512, 3, dw, db, out, 0);
}

// round 5
// speedup vs baseline: 1.3990x; 1.3990x over previous
#include <cuda_runtime.h>
#include <cfloat>

#define EPS_S   0.01f
#define INV_EPS 100.0f
#define LOG_MU  -6.93146200f   /* log(1/1024 + 1e-8) */
#define BN_EPS  1e-5f

/* ---------------- scratch (device globals: no allocs allowed) -------------- */
__device__ float g_C[4 * 1024 * 1024];
__device__ float g_u[4096], g_v[4096];
__device__ float g_rnx[4096], g_rny[4096];
__device__ float g_t[4 * 512 * 1024];
__device__ float g_a1[4 * 256 * 1024];
__device__ float g_a2[4 * 256 * 1024];
__device__ float g_alpha[4 * 512 * 1024];
__device__ float g_cm[2048], g_rs[2048];
__device__ float g_scale[512], g_shift[512];

/* ---------------- fast exp on the FMA pipe (no MUFU) ----------------
   exp(x) = e^f * 2^n, n = rint(x*log2e), f = (x*log2e - n)*ln2.
   Degree-6 Taylor on |f| <= 0.3466: rel err ~2e-7. */
__device__ __forceinline__ float fexp(float x) {
    float y = x * 1.44269504f;
    y = fmaxf(y, -126.f);
    int ni = __float2int_rn(y);
    float f = (y - (float)ni) * 0.69314718056f;
    float p = 1.3888889e-3f;
    p = fmaf(p, f, 8.3333333e-3f);
    p = fmaf(p, f, 4.1666667e-2f);
    p = fmaf(p, f, 1.6666667e-1f);
    p = fmaf(p, f, 0.5f);
    p = fmaf(p, f, 1.0f);
    p = fmaf(p, f, 1.0f);
    float s = __int_as_float((ni + 127) << 23);
    return p * s;
}

/* ---------------- small helpers ---------------- */
__device__ __forceinline__ float warpMax(float v) {
    #pragma unroll
    for (int o = 16; o; o >>= 1) v = fmaxf(v, __shfl_xor_sync(0xffffffffu, v, o));
    return v;
}
__device__ __forceinline__ float warpSum(float v) {
    #pragma unroll
    for (int o = 16; o; o >>= 1) v += __shfl_xor_sync(0xffffffffu, v, o);
    return v;
}

/* ---------------- 1/||x|| per point ---------------- */
__global__ __launch_bounds__(256) void rownorm(const float* __restrict__ x,
                                               float* __restrict__ rn) {
    int b = blockIdx.y;
    int i = blockIdx.x * 256 + threadIdx.x;
    const float* p = x + ((size_t)b * 512 << 10) + i;
    float s = 0.f;
    #pragma unroll 8
    for (int d = 0; d < 512; d++) {
        float v = p[(size_t)d << 10];
        s = fmaf(v, v, s);
    }
    rn[(b << 10) + i] = rsqrtf(s);
}

/* ---------------- SGEMM TN: C[i,j] = 1 - rnx[i]rny[j] * sum_d A[d,i]B[d,j] -- */
#define BM 128
#define BN 128
#define BK 16
__global__ __launch_bounds__(256) void gemm_tn_cost(
    const float* __restrict__ A, const float* __restrict__ B,
    const float* __restrict__ rnx, const float* __restrict__ rny,
    float* __restrict__ Cout) {
    int b = blockIdx.z;
    const float* Ab = A + (size_t)b * 512 * 1024;
    const float* Bb = B + (size_t)b * 512 * 1024;
    float* Cb = Cout + (size_t)b * 1024 * 1024;
    __shared__ float As[BK][BM];
    __shared__ float Bs[BK][BN];
    int tid = threadIdx.x;
    int tx = tid & 15, ty = tid >> 4;
    int m0 = blockIdx.x * BM, n0 = blockIdx.y * BN;
    float acc[8][8];
    #pragma unroll
    for (int i = 0; i < 8; i++)
        #pragma unroll
        for (int j = 0; j < 8; j++) acc[i][j] = 0.f;

    for (int k0 = 0; k0 < 512; k0 += BK) {
        #pragma unroll
        for (int l = 0; l < 2; l++) {
            int idx = tid + l * 256;
            int k = idx >> 5, m4 = idx & 31;
            float4 va = *(const float4*)(Ab + (size_t)(k0 + k) * 1024 + m0 + m4 * 4);
            *(float4*)&As[k][m4 * 4] = va;
            float4 vb = *(const float4*)(Bb + (size_t)(k0 + k) * 1024 + n0 + m4 * 4);
            *(float4*)&Bs[k][m4 * 4] = vb;
        }
        __syncthreads();
        #pragma unroll
        for (int k = 0; k < BK; k++) {
            float a[8], bb[8];
            *(float4*)a       = *(float4*)&As[k][ty * 8];
            *(float4*)(a + 4) = *(float4*)&As[k][ty * 8 + 4];
            *(float4*)bb       = *(float4*)&Bs[k][tx * 8];
            *(float4*)(bb + 4) = *(float4*)&Bs[k][tx * 8 + 4];
            #pragma unroll
            for (int i = 0; i < 8; i++)
                #pragma unroll
                for (int j = 0; j < 8; j++) acc[i][j] = fmaf(a[i], bb[j], acc[i][j]);
        }
        __syncthreads();
    }
    #pragma unroll
    for (int i = 0; i < 8; i++) {
        int m = m0 + ty * 8 + i;
        float rx = rnx[(b << 10) + m];
        float4 o0, o1;
        #pragma unroll
        for (int j = 0; j < 8; j++) {
            int n = n0 + tx * 8 + j;
            float v = 1.f - rx * rny[(b << 10) + n] * acc[i][j];
            if (j < 4) ((float*)&o0)[j] = v; else ((float*)&o1)[j - 4] = v;
        }
        *(float4*)(Cb + (size_t)m * 1024 + n0 + tx * 8)     = o0;
        *(float4*)(Cb + (size_t)m * 1024 + n0 + tx * 8 + 4) = o1;
    }
}

/* ---- SGEMM NT with fused pi: T[d,i] = sum_j A[d,j] * exp((u_i+v_j-C_ij)/eps)*1024 */
__global__ __launch_bounds__(256) void gemm_nt_t(
    const float* __restrict__ A,
    const float* __restrict__ Cc,
    const float* __restrict__ u, const float* __restrict__ v,
    float* __restrict__ T) {
    int b = blockIdx.z;
    const float* Ab = A + (size_t)b * 512 * 1024;
    const float* Pb = Cc + (size_t)b * 1024 * 1024;
    const float* ub = u + (b << 10);
    const float* vb = v + (b << 10);
    float* Tb = T + (size_t)b * 512 * 1024;
    __shared__ float As[BK][BM];
    __shared__ float Bs[BK][BN];
    int tid = threadIdx.x;
    int tx = tid & 15, ty = tid >> 4;
    int m0 = blockIdx.x * BM, n0 = blockIdx.y * BN;
    float acc[8][8];
    #pragma unroll
    for (int i = 0; i < 8; i++)
        #pragma unroll
        for (int j = 0; j < 8; j++) acc[i][j] = 0.f;

    for (int k0 = 0; k0 < 1024; k0 += BK) {
        #pragma unroll
        for (int l = 0; l < 2; l++) {
            int idx = tid + l * 256;
            int m = idx >> 2, k4 = idx & 3;
            float4 va = *(const float4*)(Ab + (size_t)(m0 + m) * 1024 + k0 + k4 * 4);
            As[k4 * 4 + 0][m] = va.x; As[k4 * 4 + 1][m] = va.y;
            As[k4 * 4 + 2][m] = va.z; As[k4 * 4 + 3][m] = va.w;
            float4 vc = *(const float4*)(Pb + (size_t)(n0 + m) * 1024 + k0 + k4 * 4);
            float ui = ub[n0 + m];
            float4 vv = *(const float4*)(vb + k0 + k4 * 4);
            Bs[k4 * 4 + 0][m] = fexp((ui + vv.x - vc.x) * INV_EPS) * 1024.f;
            Bs[k4 * 4 + 1][m] = fexp((ui + vv.y - vc.y) * INV_EPS) * 1024.f;
            Bs[k4 * 4 + 2][m] = fexp((ui + vv.z - vc.z) * INV_EPS) * 1024.f;
            Bs[k4 * 4 + 3][m] = fexp((ui + vv.w - vc.w) * INV_EPS) * 1024.f;
        }
        __syncthreads();
        #pragma unroll
        for (int k = 0; k < BK; k++) {
            float a[8], bb[8];
            *(float4*)a       = *(float4*)&As[k][ty * 8];
            *(float4*)(a + 4) = *(float4*)&As[k][ty * 8 + 4];
            *(float4*)bb       = *(float4*)&Bs[k][tx * 8];
            *(float4*)(bb + 4) = *(float4*)&Bs[k][tx * 8 + 4];
            #pragma unroll
            for (int i = 0; i < 8; i++)
                #pragma unroll
                for (int j = 0; j < 8; j++) acc[i][j] = fmaf(a[i], bb[j], acc[i][j]);
        }
        __syncthreads();
    }
    #pragma unroll
    for (int i = 0; i < 8; i++) {
        int m = m0 + ty * 8 + i;
        float4 o0, o1;
        #pragma unroll
        for (int j = 0; j < 8; j++) {
            float vvv = acc[i][j];
            if (j < 4) ((float*)&o0)[j] = vvv; else ((float*)&o1)[j - 4] = vvv;
        }
        *(float4*)(Tb + (size_t)m * 1024 + n0 + tx * 8)     = o0;
        *(float4*)(Tb + (size_t)m * 1024 + n0 + tx * 8 + 4) = o1;
    }
}

/* ---------------- Sinkhorn ---------------- */
__global__ void zero_uv(float* u, float* v) {
    int i = blockIdx.x * blockDim.x + threadIdx.x;
    if (i < 4096) { u[i] = 0.f; v[i] = 0.f; }
}

__global__ __launch_bounds__(256) void u_update(const float* __restrict__ C,
                                                const float* __restrict__ v,
                                                float* __restrict__ u) {
    int b = blockIdx.y, i = blockIdx.x, t = threadIdx.x;
    const float4* C4 = (const float4*)(C + ((size_t)(b << 10) + i) * 1024);
    const float4* V4 = (const float4*)(v + (b << 10));
    float4 c = C4[t], vv = V4[t];
    float x0 = (vv.x - c.x) * INV_EPS;
    float x1 = (vv.y - c.y) * INV_EPS;
    float x2 = (vv.z - c.z) * INV_EPS;
    float x3 = (vv.w - c.w) * INV_EPS;
    float mx = fmaxf(fmaxf(x0, x1), fmaxf(x2, x3));
    __shared__ float redm[8], redq[8];
    mx = warpMax(mx);
    if ((t & 31) == 0) redm[t >> 5] = mx;
    __syncthreads();
    if (t < 32) {
        float z = (t < 8) ? redm[t] : -FLT_MAX;
        #pragma unroll
        for (int o = 4; o; o >>= 1) z = fmaxf(z, __shfl_xor_sync(0xffffffffu, z, o));
        if (t == 0) redm[0] = z;
    }
    __syncthreads();
    float bm = redm[0];
    float s = fexp(x0 - bm) + fexp(x1 - bm) + fexp(x2 - bm) + fexp(x3 - bm);
    s = warpSum(s);
    if ((t & 31) == 0) redq[t >> 5] = s;
    __syncthreads();
    if (t == 0) {
        float z = 0.f;
        #pragma unroll
        for (int q = 0; q < 8; q++) z += redq[q];
        u[(b << 10) + i] = EPS_S * (LOG_MU - (bm + __logf(z)));
    }
}

__global__ __launch_bounds__(256) void v_update(const float* __restrict__ C,
                                                const float* __restrict__ u,
                                                float* __restrict__ v) {
    int b = blockIdx.y;
    int tx = threadIdx.x, ty = threadIdx.y;
    int j = blockIdx.x * 32 + tx;
    const float* p = C + (size_t)b * 1048576 + j;
    const float* ub = u + (b << 10);
    float m0 = -FLT_MAX, s0 = 0.f, m1 = -FLT_MAX, s1 = 0.f;
    for (int i = ty; i < 1024; i += 16) {
        float xa = (ub[i] - p[(size_t)i << 10]) * INV_EPS;
        float xb = (ub[i + 8] - p[(size_t)(i + 8) << 10]) * INV_EPS;
        float n0 = fmaxf(m0, xa);
        s0 = s0 * fexp(m0 - n0) + fexp(xa - n0); m0 = n0;
        float n1 = fmaxf(m1, xb);
        s1 = s1 * fexp(m1 - n1) + fexp(xb - n1); m1 = n1;
    }
    float mm = fmaxf(m0, m1);
    float ss = s0 * fexp(m0 - mm) + s1 * fexp(m1 - mm);
    __shared__ float sm[8][32], sq[8][32];
    sm[ty][tx] = mm; sq[ty][tx] = ss;
    __syncthreads();
    if (ty == 0) {
        float M = mm, S = ss;
        #pragma unroll
        for (int q = 1; q < 8; q++) {
            float m2 = sm[q][tx], s2 = sq[q][tx];
            float nm = fmaxf(M, m2);
            S = S * fexp(M - nm) + s2 * fexp(m2 - nm);
            M = nm;
        }
        v[(b << 10) + j] = EPS_S * (LOG_MU - (M + __logf(S)));
    }
}

/* ---------------- per-(b,c) mean / 1/std of content ---------------- */
__global__ __launch_bounds__(128) void cmstd(const float* __restrict__ x,
                                             float* __restrict__ cm,
                                             float* __restrict__ rs) {
    int bc = blockIdx.x, t = threadIdx.x;
    const float* p = x + ((size_t)bc << 10);
    float s = 0.f, q = 0.f;
    #pragma unroll
    for (int l = 0; l < 8; l++) {
        float v = p[t + l * 128];
        s += v; q = fmaf(v, v, q);
    }
    s = warpSum(s); q = warpSum(q);
    __shared__ float rsm[4], rqm[4];
    if ((t & 31) == 0) { rsm[t >> 5] = s; rqm[t >> 5] = q; }
    __syncthreads();
    if (t == 0) {
        float S = rsm[0] + rsm[1] + rsm[2] + rsm[3];
        float Q = rqm[0] + rqm[1] + rqm[2] + rqm[3];
        float mean = S * (1.f / 1024.f);
        float var = Q * (1.f / 1024.f) - mean * mean;
        cm[bc] = mean;
        rs[bc] = rsqrtf(fmaxf(var, 0.f) + 1e-5f);
    }
}

/* ---------------- BatchNorm stats (train mode): scale/shift ---------------- */
__global__ __launch_bounds__(256) void bnstats(const float* __restrict__ x,
                                               const float* __restrict__ g,
                                               const float* __restrict__ be,
                                               int CO, float* __restrict__ scale,
                                               float* __restrict__ shift) {
    int c = blockIdx.x, t = threadIdx.x;
    float s = 0.f, q = 0.f;
    #pragma unroll
    for (int l = 0; l < 16; l++) {
        int idx = t + (l << 8);
        int bb = idx >> 10, p = idx & 1023;
        float v = x[((size_t)(bb * CO + c) << 10) + p];
        s += v; q = fmaf(v, v, q);
    }
    s = warpSum(s); q = warpSum(q);
    __shared__ float rsm[8], rqm[8];
    if ((t & 31) == 0) { rsm[t >> 5] = s; rqm[t >> 5] = q; }
    __syncthreads();
    if (t == 0) {
        float S = 0.f, Q = 0.f;
        #pragma unroll
        for (int w = 0; w < 8; w++) { S += rsm[w]; Q += rqm[w]; }
        float mean = S * (1.f / 4096.f);
        float var = Q * (1.f / 4096.f) - mean * mean;
        float sc = g[c] * rsqrtf(fmaxf(var, 0.f) + BN_EPS);
        scale[c] = sc;
        shift[c] = be[c] - mean * sc;
    }
}

/* ---------------- direct 3x3 conv, smem plane tiles (R3 structure) ----------
   optional fused per-input-channel affine (BN apply), optional fused blend
   (decoder: in = t + alpha*(content-cm)*rs) applied during smem fill.        */
template <int OCT, int SROWS, int NT, int CIT>
__global__ __launch_bounds__(NT) void conv3x3(
    const float* __restrict__ src0, const float* __restrict__ src1, int csplit,
    const float* __restrict__ sc, const float* __restrict__ sh,
    const float* __restrict__ bl_a, const float* __restrict__ bl_x,
    const float* __restrict__ bl_cm, const float* __restrict__ bl_rs,
    int CI, int CO, const float* __restrict__ W, const float* __restrict__ bias,
    float* __restrict__ out, int relu) {
    constexpr int NPIX = SROWS * 32;
    constexpr int PXT = NPIX / NT;
    __shared__ float s_in[CIT][SROWS + 2][34];
    __shared__ float s_w[CIT][9][OCT];
    int b = blockIdx.x, oc0 = blockIdx.y * OCT, r0 = blockIdx.z * SROWS;
    int tid = threadIdx.x;
    int rr[PXT], cc[PXT];
    #pragma unroll
    for (int p = 0; p < PXT; p++) {
        int px = tid + p * NT;
        rr[p] = px >> 5; cc[p] = px & 31;
    }
    float acc[OCT][PXT];
    #pragma unroll
    for (int o = 0; o < OCT; o++)
        #pragma unroll
        for (int p = 0; p < PXT; p++) acc[o][p] = 0.f;

    const int TOTIN = CIT * (SROWS + 2) * 34;
    const int TW = CIT * 9 * OCT;
    int use_aff = (sc != nullptr);
    int use_blend = (bl_a != nullptr);

    #pragma unroll 1
    for (int ci0 = 0; ci0 < CI; ci0 += CIT) {
        #pragma unroll 1
        for (int idx = tid; idx < TOTIN; idx += NT) {
            int ci = idx / ((SROWS + 2) * 34);
            int rem = idx - ci * ((SROWS + 2) * 34);
            int r = rem / 34, c = rem - r * 34;
            int gy = r0 + r - 1, gx = c - 1;
            float v = 0.f;
            if ((unsigned)gy < 32u && (unsigned)gx < 32u) {
                int cig = ci0 + ci;
                int pix = (gy << 5) + gx;
                const float* s = (cig < csplit)
                    ? (src0 + ((size_t)(b * csplit + cig) << 10))
                    : (src1 + ((size_t)(b * (CI - csplit) + (cig - csplit)) << 10));
                v = s[pix];
                if (use_aff) v = fmaf(v, sc[cig], sh[cig]);
                if (use_blend) {
                    int ch = b * CI + cig;
                    size_t off = ((size_t)ch << 10) + pix;
                    v = fmaf(bl_a[off], (bl_x[off] - bl_cm[ch]) * bl_rs[ch], v);
                }
            }
            (&s_in[0][0][0])[idx] = v;
        }
        #pragma unroll 1
        for (int idx = tid; idx < TW; idx += NT) {
            int ci = idx / (9 * OCT);
            int rem = idx - ci * (9 * OCT);
            int k = rem / OCT, oc = rem - k * OCT;
            float wv = 0.f;
            if (oc0 + oc < CO)
                wv = W[((size_t)(oc0 + oc) * CI + ci0 + ci) * 9 + k];
            (&s_w[0][0][0])[idx] = wv;
        }
        __syncthreads();
        #pragma unroll 1
        for (int ci = 0; ci < CIT; ci++) {
            #pragma unroll
            for (int ky = 0; ky < 3; ky++)
                #pragma unroll
                for (int kx = 0; kx < 3; kx++) {
                    float w[OCT];
                    #pragma unroll
                    for (int o4 = 0; o4 < OCT / 4; o4++)
                        *(float4*)&w[o4 * 4] = *(const float4*)&s_w[ci][ky * 3 + kx][o4 * 4];
                    #pragma unroll
                    for (int p = 0; p < PXT; p++) {
                        float v = s_in[ci][rr[p] + ky][cc[p] + kx];
                        #pragma unroll
                        for (int o = 0; o < OCT; o++)
                            acc[o][p] = fmaf(v, w[o], acc[o][p]);
                    }
                }
        }
        __syncthreads();
    }
    #pragma unroll
    for (int o = 0; o < OCT; o++) {
        if (oc0 + o >= CO) break;
        float bi = bias[oc0 + o];
        #pragma unroll
        for (int p = 0; p < PXT; p++) {
            float v = acc[o][p] + bi;
            if (relu) v = fmaxf(v, 0.f);
            out[((size_t)(b * CO + oc0 + o) << 10) + r0 * 32 + tid + p * NT] = v;
        }
    }
}

/* ---------------- host orchestration ---------------- */
extern "C" void kernel_launch(void* const* d_in, const int* in_sizes, int n_in,
                              void* d_out, int out_size) {
    const float* content = (const float*)d_in[0];
    const float* style   = (const float*)d_in[1];
    const float* w1 = (const float*)d_in[2];  const float* b1 = (const float*)d_in[3];
    const float* g1 = (const float*)d_in[4];  const float* be1 = (const float*)d_in[5];
    const float* w2 = (const float*)d_in[6];  const float* b2 = (const float*)d_in[7];
    const float* g2 = (const float*)d_in[8];  const float* be2 = (const float*)d_in[9];
    const float* w3 = (const float*)d_in[10]; const float* b3 = (const float*)d_in[11];
    const float* dw = (const float*)d_in[12]; const float* db = (const float*)d_in[13];
    float* out = (float*)d_out;
    (void)in_sizes; (void)n_in; (void)out_size;

    float *pC, *pu, *pv, *prnx, *prny, *pt, *pa1, *pa2, *palpha, *pcm, *prs, *pscale, *pshift;
    cudaGetSymbolAddress((void**)&pC, g_C);
    cudaGetSymbolAddress((void**)&pu, g_u);
    cudaGetSymbolAddress((void**)&pv, g_v);
    cudaGetSymbolAddress((void**)&prnx, g_rnx);
    cudaGetSymbolAddress((void**)&prny, g_rny);
    cudaGetSymbolAddress((void**)&pt, g_t);
    cudaGetSymbolAddress((void**)&pa1, g_a1);
    cudaGetSymbolAddress((void**)&pa2, g_a2);
    cudaGetSymbolAddress((void**)&palpha, g_alpha);
    cudaGetSymbolAddress((void**)&pcm, g_cm);
    cudaGetSymbolAddress((void**)&prs, g_rs);
    cudaGetSymbolAddress((void**)&pscale, g_scale);
    cudaGetSymbolAddress((void**)&pshift, g_shift);

    /* cosine-cost matrix */
    rownorm<<<dim3(4, 4), 256>>>(content, prnx);
    rownorm<<<dim3(4, 4), 256>>>(style, prny);
    gemm_tn_cost<<<dim3(8, 8, 4), 256>>>(content, style, prnx, prny, pC);

    /* Sinkhorn, 20 iterations (exp on FMA pipe) */
    zero_uv<<<16, 256>>>(pu, pv);
    for (int it = 0; it < 20; it++) {
        u_update<<<dim3(1024, 4), 256>>>(pC, pv, pu);
        v_update<<<dim3(32, 4), dim3(32, 8)>>>(pC, pu, pv);
    }

    /* t = pi @ style_points, exp fused into B-tile load */
    gemm_nt_t<<<dim3(4, 8, 4), 256>>>(style, pC, pu, pv, pt);

    /* content per-channel mean/std */
    cmstd<<<2048, 128>>>(content, pcm, prs);

    /* alpha predictor (BN-apply fused into next conv's input load) */
    conv3x3<8, 16, 256, 8><<<dim3(4, 32, 2), 256>>>(pt, content, 512,
        nullptr, nullptr, nullptr, nullptr, nullptr, nullptr,
        1024, 256, w1, b1, pa1, 1);
    bnstats<<<256, 256>>>(pa1, g1, be1, 256, pscale, pshift);
    conv3x3<8, 16, 256, 8><<<dim3(4, 32, 2), 256>>>(pa1, pa1, 256,
        pscale, pshift, nullptr, nullptr, nullptr, nullptr,
        256, 256, w2, b2, pa2, 1);
    bnstats<<<256, 256>>>(pa2, g2, be2, 256, pscale, pshift);
    conv3x3<8, 16, 256, 8><<<dim3(4, 64, 2), 256>>>(pa2, pa2, 256,
        pscale, pshift, nullptr, nullptr, nullptr, nullptr,
        256, 512, w3, b3, palpha, 0);

    /* decoder conv with fused blend: in = t + alpha*(content-cm)*rs */
    conv3x3<4, 4, 128, 8><<<dim3(4, 1, 8), 128>>>(pt, pt, 512,
        nullptr, nullptr, palpha, content, pcm, prs,
        512, 3, dw, db, out, 0);
}